// round 14
// baseline (speedup 1.0000x reference)
#include <cuda_runtime.h>
#include <cstdint>
#include <cstddef>

#define B_ 256
#define S_ 512
#define T_ 128

typedef unsigned long long ull;

__device__ float g_acc;        // zero-init; reset by last CTA each run
__device__ unsigned g_done;    // zero-init; reset by last CTA each run

// Packed fp32x2 ops (sm_103a).
#define FMA2(d, a, b, c) asm("fma.rn.f32x2 %0, %1, %2, %3;" : "=l"(d) : "l"(a), "l"(b), "l"(c))
#define ADD2(d, a, b)    asm("add.rn.f32x2 %0, %1, %2;"     : "=l"(d) : "l"(a), "l"(b))
#define PACK2(d, lo, hi) asm("mov.b64 %0, {%1, %2};"        : "=l"(d) : "f"(lo), "f"(hi))
#define UNPK2(lo, hi, s) asm("mov.b64 {%0, %1}, %2;"        : "=f"(lo), "=f"(hi) : "l"(s))

// ---------------------------------------------------------------------------
// Fully fused CRF. 1 batch per CTA (grid 256), 256 threads, 2 CTAs/SM
// -> 4 warps/SMSP for latency hiding. Thread (h = tid>>7, j = tid&127)
// computes the half-dot over rows [64h, 64h+64): per-warp Mc is 32 f32x2
// (64 regs), so ~110 regs/thread and occupancy 2 actually holds (unlike the
// 255-reg full-column variant). All alpha/partial LDS are warp-uniform
// broadcasts or conflict-free coalesced. Rescale by alpha_prev[0] every 4th
// step only (worst-case growth ~e^54 << fp32 max e^88). Two barriers/step:
// partial-combine and alpha-publish.
// ---------------------------------------------------------------------------
__global__ void __launch_bounds__(256, 2) crf_fused(
    const float* __restrict__ em, const float* __restrict__ tr,
    const void* __restrict__ tags, const unsigned char* __restrict__ mask,
    float* __restrict__ out) {

    __shared__ __align__(16) float s_alpha[2][T_];   // [buf][col]
    __shared__ __align__(16) float s_part[2][T_];    // [half][col]
    __shared__ float s_red[8];
    __shared__ int   s_flags[2];

    const int tid  = threadIdx.x;
    const int j    = tid & 127;      // output column
    const int h    = tid >> 7;       // row half: rows [64h, 64h+64)
    const int w    = tid >> 5;
    const int lane = tid & 31;
    const size_t b = blockIdx.x;

    // ---- dtype probe (JAX x64-off downcasts int64 tags to int32) ----------
    // tags < 128 => int64 buffer has all odd int32 words zero; P(fp) ~128^-64.
    if (tid == 0) {
        const int* t32 = (const int*)tags;
        int all0 = 1;
        #pragma unroll
        for (int i = 0; i < 64; ++i)
            if (t32[2 * i + 1] != 0) all0 = 0;
        s_flags[0] = all0;
        const unsigned char* mk = mask;
        s_flags[1] = (mk[0] != 0 && mk[1] == 0 && mk[2] == 0 && mk[3] == 0) ? 4 : 1;
    }
    __syncthreads();
    const int t64 = s_flags[0], mst = s_flags[1];

    // ---- gold score for this batch (negated into g_acc) --------------------
    {
        const long long* tg64 = (const long long*)tags + b * S_;
        const int*       tg32 = (const int*)tags + b * S_;
        const unsigned char* mk = mask + b * S_ * mst;
        float sum = 0.0f;
        for (int t = tid; t < S_; t += 256) {
            int tag = t64 ? (int)tg64[t] : tg32[t];
            float m = mk[(size_t)t * mst] ? 1.0f : 0.0f;
            sum += em[(b * S_ + t) * T_ + tag] * m;
            if (t + 1 < S_) {
                int tag2 = t64 ? (int)tg64[t + 1] : tg32[t + 1];
                float m2 = mk[(size_t)(t + 1) * mst] ? 1.0f : 0.0f;
                sum += tr[tag * T_ + tag2] * m2;
            }
        }
        for (int off = 16; off; off >>= 1)
            sum += __shfl_xor_sync(0xffffffffu, sum, off);
        if (lane == 0) s_red[w] = sum;
        __syncthreads();
        if (tid == 0) {
            float s = 0.0f;
            #pragma unroll
            for (int k = 0; k < 8; ++k) s += s_red[k];
            atomicAdd(&g_acc, -s);
        }
        __syncthreads();   // s_red reused at the end
    }

    // ---- Mc: half-column rows [64h, 64h+64) of column j, packed pairs ------
    ull Mc[32];
    {
        const int r0 = 64 * h;
        #pragma unroll
        for (int k = 0; k < 32; ++k) {
            float m0 = expf(tr[(r0 + 2 * k) * T_ + j]);
            float m1 = expf(tr[(r0 + 2 * k + 1) * T_ + j]);
            PACK2(Mc[k], m0, m1);
        }
    }

    // ---- init: alpha_0 = exp(e0), logacc = 0 (no reduction) ----------------
    float e0 = em[(b * S_ + 0) * T_ + j];
    s_alpha[0][j] = __expf(e0);       // dual-write (h=0/1), bit-exact same value
    float logacc = 0.0f;              // uniform across CTA

    // emission prefetch ring (3 deep); h duplicates hit L1
    float ec = em[(b * S_ + 1) * T_ + j];
    float en = em[(b * S_ + 2) * T_ + j];
    float ef = em[(b * S_ + 3) * T_ + j];
    __syncthreads();

    // ---- main recursion ----------------------------------------------------
    float v = 0.0f;
    #pragma unroll 1
    for (int t = 1; t < S_; ++t) {
        const int rb = (t - 1) & 1, wb = t & 1;

        // periodic CTA-uniform rescale from previous alpha[0] (broadcast LDS)
        float sc = 1.0f;
        if ((t & 3) == 1) {
            float c = s_alpha[rb][0];
            sc = __fdividef(1.0f, c);
            logacc += __logf(c);
        }

        // fire next prefetch LDG early so DRAM latency hides under FMA block
        int t3 = (t + 3 < S_) ? t + 3 : S_ - 1;
        float eg = em[(b * S_ + t3) * T_ + j];

        float ex = __expf(ec);

        // half-dot: 16 broadcast LDS.128 + 32 FMA2 in 4 chains (depth 8)
        const ulonglong2* A = (const ulonglong2*)&s_alpha[rb][64 * h];
        ull a0 = 0ull, a1 = 0ull, a2 = 0ull, a3 = 0ull;
        #pragma unroll
        for (int k = 0; k < 16; k += 2) {
            ulonglong2 x0 = A[k];
            ulonglong2 x1 = A[k + 1];
            FMA2(a0, x0.x, Mc[4 * (k / 2)],     a0);
            FMA2(a1, x0.y, Mc[4 * (k / 2) + 1], a1);
            FMA2(a2, x1.x, Mc[4 * (k / 2) + 2], a2);
            FMA2(a3, x1.y, Mc[4 * (k / 2) + 3], a3);
        }
        ADD2(a0, a0, a1); ADD2(a2, a2, a3); ADD2(a0, a0, a2);
        float lo, hi;
        UNPK2(lo, hi, a0);
        float p = (lo + hi) * sc * ex;   // fold scale+emission pre-barrier

        s_part[h][j] = p;
        __syncthreads();                 // barrier A: partials visible

        // redundant combine on both halves (bit-exact), dual-write alpha
        v = s_part[0][j] + s_part[1][j];
        s_alpha[wb][j] = v;

        // rotate ring
        ec = en; en = ef; ef = eg;
        __syncthreads();                 // barrier B: alpha visible for t+1
    }

    // ---- finish: partition_b = log(sum_j v) + logacc (h=0 threads) ---------
    float s = (h == 0) ? v : 0.0f;
    for (int off = 16; off; off >>= 1)
        s += __shfl_xor_sync(0xffffffffu, s, off);
    if (lane == 0) s_red[w] = s;
    __syncthreads();
    if (tid == 0) {
        float tot = 0.0f;
        #pragma unroll
        for (int k = 0; k < 8; ++k) tot += s_red[k];
        atomicAdd(&g_acc, logf(tot) + logacc);
        __threadfence();
        unsigned r = atomicAdd(&g_done, 1u);
        if (r == B_ - 1) {                 // last CTA: publish + reset
            float res = atomicExch(&g_acc, 0.0f);
            out[0] = res;
            atomicExch(&g_done, 0u);
        }
    }
}

extern "C" void kernel_launch(void* const* d_in, const int* in_sizes, int n_in,
                              void* d_out, int out_size) {
    const float* em         = (const float*)d_in[0];
    const void* tags        = d_in[1];
    const unsigned char* mk = (const unsigned char*)d_in[2];
    const float* tr         = (const float*)d_in[3];

    crf_fused<<<B_, 256>>>(em, tr, tags, mk, (float*)d_out);
}